// round 1
// baseline (speedup 1.0000x reference)
#include <cuda_runtime.h>

// Shapes (fixed by the problem)
#define B_  32
#define C_  256
#define HW_ 3136        // 56*56
#define HW4 784         // HW_/4 float4 per plane
#define TOTAL4 (2 * B_ * C_ * HW4)   // 12,845,056 float4 total output
#define COPY_THREADS 256
#define COPY_UNROLL 4
#define COPY_BLOCKS (TOTAL4 / (COPY_THREADS * COPY_UNROLL))  // 12544, exact

// Channel-exchange maps, filled by build_map, read by exchange_copy.
// g_srcChan[w][c] = source channel; g_srcSel[w][c] = 0 -> read x1, 1 -> read x2
__device__ int g_srcChan[2][C_];
__device__ int g_srcSel[2][C_];

// ---------------------------------------------------------------------------
// Kernel A: one block of 256 threads computes the full channel mapping.
//   order = stable argsort of -|w|  (descending, ties by ascending index)
//   rank  = clip(cumsum(|w| < thr) - 1, 0)
//   src_for1 = order2[rank1] ; src_for2 = order1[rank2]
// ---------------------------------------------------------------------------
__global__ void build_map(const float* __restrict__ w1,
                          const float* __restrict__ w2,
                          const float* __restrict__ thr_p) {
    __shared__ float a1[C_], a2[C_];
    __shared__ int order1[C_], order2[C_];
    __shared__ int bel1s[C_], bel2s[C_];

    const int c = threadIdx.x;
    const float thr = thr_p[0];
    const float v1 = fabsf(w1[c]);
    const float v2 = fabsf(w2[c]);
    a1[c] = v1;
    a2[c] = v2;
    __syncthreads();

    // Stable descending rank by counting (O(256) per thread)
    int r1 = 0, r2 = 0;
#pragma unroll 8
    for (int j = 0; j < C_; j++) {
        const float b1 = a1[j], b2 = a2[j];
        r1 += (b1 > v1) || (b1 == v1 && j < c);
        r2 += (b2 > v2) || (b2 == v2 && j < c);
    }
    order1[r1] = c;
    order2[r2] = c;
    bel1s[c] = (v1 < thr);
    bel2s[c] = (v2 < thr);
    __syncthreads();

    // Inclusive prefix count of "below" flags up to c
    int cum1 = 0, cum2 = 0;
    for (int j = 0; j <= c; j++) { cum1 += bel1s[j]; cum2 += bel2s[j]; }
    const int rank1 = max(cum1 - 1, 0);
    const int rank2 = max(cum2 - 1, 0);

    const int s1 = order2[rank1];   // source channel in x2 for feature1
    const int s2 = order1[rank2];   // source channel in x1 for feature2
    const bool bl1 = bel1s[c] != 0;
    const bool bl2 = bel2s[c] != 0;

    // feature1[:,c] = bl1 ? x2[:, s1] : x1[:, c]
    g_srcChan[0][c] = bl1 ? s1 : c;
    g_srcSel [0][c] = bl1 ? 1 : 0;
    // feature2[:,c] = bl2 ? x1[:, s2] : x2[:, c]
    g_srcChan[1][c] = bl2 ? s2 : c;
    g_srcSel [1][c] = bl2 ? 0 : 1;
}

// ---------------------------------------------------------------------------
// Kernel B: HBM-bound gather-copy. Flat index over all output float4s.
// Output layout: feature1 (B,C,H,W) followed by feature2 (B,C,H,W).
// ---------------------------------------------------------------------------
__global__ __launch_bounds__(COPY_THREADS)
void exchange_copy(const float4* __restrict__ x1,
                   const float4* __restrict__ x2,
                   float4* __restrict__ out) {
    const int base = blockIdx.x * (COPY_THREADS * COPY_UNROLL) + threadIdx.x;
#pragma unroll
    for (int k = 0; k < COPY_UNROLL; k++) {
        const int idx = base + k * COPY_THREADS;       // < TOTAL4, exact
        const int p   = idx / HW4;                     // plane id: [0, 2*B*C)
        const int hw  = idx - p * HW4;                 // float4 offset in plane
        const int which = p >> 13;                     // 0: feature1, 1: feature2 (B*C=8192)
        const int c = p & (C_ - 1);
        const int b = (p >> 8) & (B_ - 1);

        const int sc  = g_srcChan[which][c];
        const int sel = g_srcSel [which][c];
        const float4* __restrict__ src = sel ? x2 : x1;
        out[idx] = src[(b * C_ + sc) * HW4 + hw];
    }
}

extern "C" void kernel_launch(void* const* d_in, const int* in_sizes, int n_in,
                              void* d_out, int out_size) {
    const float* x1  = (const float*)d_in[0];
    const float* x2  = (const float*)d_in[1];
    const float* w1  = (const float*)d_in[2];
    const float* w2  = (const float*)d_in[3];
    const float* thr = (const float*)d_in[4];

    build_map<<<1, C_>>>(w1, w2, thr);
    exchange_copy<<<COPY_BLOCKS, COPY_THREADS>>>(
        (const float4*)x1, (const float4*)x2, (float4*)d_out);
}